// round 17
// baseline (speedup 1.0000x reference)
#include <cuda_runtime.h>
#include <cuda_fp16.h>

typedef unsigned int u32;

#define B_DIM 16
#define C_DIM 64
#define K_DIM 207
#define KL 13248            /* 207*64 */
#define KK 42849            /* 207*207 */
#define KP 256              /* padded k */
#define KLP 16384           /* KP*64 padded plane */

// fp16 scratch (allocation-free rule: __device__ globals; zero-init at load,
// rows never written stay zero — relied on for j/k padding)
__device__ __half g_x16[(size_t)B_DIM*C_DIM*KLP];
__device__ __half g_t16[(size_t)4*B_DIM*C_DIM*KLP];
__device__ __half g_ah[(size_t)2*B_DIM*KP*KP];
__device__ __half g_al[(size_t)2*B_DIM*KP*KP];
__device__ __half g_wh[64*320];

// ---------------------------------------------------------------- helpers
__device__ __forceinline__ u32 smem_u32(const void* p) {
    u32 a;
    asm("{ .reg .u64 t; cvta.to.shared.u64 t, %1; cvt.u32.u64 %0, t; }" : "=r"(a) : "l"(p));
    return a;
}
// pack {lo: v0, hi: v1} as f16x2
__device__ __forceinline__ u32 cvt2h(float v0, float v1) {
    u32 r; asm("cvt.rn.f16x2.f32 %0, %1, %2;" : "=r"(r) : "f"(v1), "f"(v0)); return r;
}
__device__ __forceinline__ void ldsm4(u32& r0,u32& r1,u32& r2,u32& r3, u32 a){
    asm volatile("ldmatrix.sync.aligned.m8n8.x4.shared.b16 {%0,%1,%2,%3}, [%4];"
        : "=r"(r0),"=r"(r1),"=r"(r2),"=r"(r3) : "r"(a) : "memory");
}
__device__ __forceinline__ void ldsm4t(u32& r0,u32& r1,u32& r2,u32& r3, u32 a){
    asm volatile("ldmatrix.sync.aligned.m8n8.x4.trans.shared.b16 {%0,%1,%2,%3}, [%4];"
        : "=r"(r0),"=r"(r1),"=r"(r2),"=r"(r3) : "r"(a) : "memory");
}
__device__ __forceinline__ void mma_h(float* c, const u32* a, const u32* b){
    asm("mma.sync.aligned.m16n8k16.row.col.f32.f16.f16.f32 "
        "{%0,%1,%2,%3}, {%4,%5,%6,%7}, {%8,%9}, {%0,%1,%2,%3};"
        : "+f"(c[0]),"+f"(c[1]),"+f"(c[2]),"+f"(c[3])
        : "r"(a[0]),"r"(a[1]),"r"(a[2]),"r"(a[3]), "r"(b[0]),"r"(b[1]));
}
// XOR swizzles for 128B / 512B row strides
__device__ __forceinline__ u32 swz128(u32 o){ return o ^ ((o >> 3) & 0x70); }
__device__ __forceinline__ u32 swz512(u32 o){ return o ^ ((o >> 5) & 0x70); }

__device__ __forceinline__ void cpa16(u32 s, const void* g){
    asm volatile("cp.async.cg.shared.global [%0], [%1], 16;" :: "r"(s), "l"(g));
}
#define CP_COMMIT() asm volatile("cp.async.commit_group;" ::: "memory")
#define CP_WAIT1()  asm volatile("cp.async.wait_group 1;" ::: "memory")
#define CP_WAIT0()  asm volatile("cp.async.wait_group 0;" ::: "memory")

// ================= prep: fp32 -> fp16 (hi/lo split for A only) ==============
__global__ __launch_bounds__(256) void prep_x(const float* __restrict__ x) {
    size_t pe = ((size_t)blockIdx.x*256 + threadIdx.x) * 2;   // over B*C*KLP
    size_t plane = pe >> 14;
    int r = (int)(pe & 16383), k = r >> 6, l = r & 63;
    float v0 = 0.f, v1 = 0.f;
    if (k < K_DIM) {
        float2 v = *(const float2*)(x + plane*KL + (size_t)k*64 + l);
        v0 = v.x; v1 = v.y;
    }
    *(u32*)(g_x16 + pe) = cvt2h(v0, v1);
}
__global__ __launch_bounds__(256) void prep_a(
    const float* __restrict__ a0, const float* __restrict__ a1) {
    size_t pe = ((size_t)blockIdx.x*256 + threadIdx.x) * 2;   // over 2*B_DIM*KP*KP
    int sb = (int)(pe >> 16);
    int r = (int)(pe & 65535), j = r >> 8, k = r & 255;
    int s = sb >> 4, b = sb & 15;
    const float* A = (s ? a1 : a0) + (size_t)b*KK + (size_t)j*K_DIM;
    float v0 = (j < K_DIM && k     < K_DIM) ? A[k]     : 0.f;
    float v1 = (j < K_DIM && k + 1 < K_DIM) ? A[k + 1] : 0.f;
    float h0 = __half2float(__float2half_rn(v0));
    float h1 = __half2float(__float2half_rn(v1));
    *(u32*)(g_ah + pe) = cvt2h(h0, h1);
    *(u32*)(g_al + pe) = cvt2h(v0 - h0, v1 - h1);
}
__global__ __launch_bounds__(256) void prep_w(const float* __restrict__ W) {
    size_t pe = ((size_t)blockIdx.x*256 + threadIdx.x) * 2;   // over 64*320
    float2 v = *(const float2*)(W + pe);
    *(u32*)(g_wh + pe) = cvt2h(v.x, v.y);
}

// ================= diffuse: t[m][b][c][j][l] = sum_k M[j,k] src[c][k][l] ====
// pass0: src = g_x16, dst m=2s, (Ah+Al)*X; pass1: src = g_t16[2s], dst m=2s+1, Ah*X.
// CTA: 128 j x 256 n (4 ch x 64 l), 8 warps 64x64. DB'd K chunks of 64. 1 CTA/SM.
#define DF_AH 0         /* [128 j][64 k] fp16, 128B rows */
#define DF_AL 16384
#define DF_X  32768     /* [64 k][256 n] fp16, 512B rows */
#define DF_SZ 65536
#define DF_SMEM (2*DF_SZ)

__global__ __launch_bounds__(256, 1) void diffuse_mma(int pass)
{
    extern __shared__ char smn[];
    const u32 sb = smem_u32(smn);
    const int tid = threadIdx.x, lane = tid & 31, wid = tid >> 5;
    const int nt = blockIdx.x & 15, jt = blockIdx.x >> 4;
    const int s = blockIdx.y, b = blockIdx.z;
    const int j0 = jt*128;
    const int jm0 = (wid >> 2)*64, n0 = (wid & 3)*64, warp_n = wid & 3;
    const bool full = (j0 + jm0 + 64 <= 208);   // all 4 M-frags contain real rows
    const int np = pass ? 1 : 2;

    const __half* AH = g_ah + (size_t)(s*B_DIM + b)*KP*KP;
    const __half* AL = g_al + (size_t)(s*B_DIM + b)*KP*KP;
    const __half* X = (pass
        ? g_t16 + (size_t)((2*s)*B_DIM + b)*C_DIM*KLP
        : g_x16 + (size_t)b*C_DIM*KLP) + (size_t)(nt*4)*KLP;

    auto stage = [&](int chunk, u32 sbuf){
        const int kc = chunk*64;
        #pragma unroll
        for (int it = 0; it < 4; ++it) {          // A: 128 rows x 128B (hi, +lo p0)
            int e = tid + it*256;
            int j = e >> 3, q = e & 7;
            size_t go = (size_t)(j0 + j)*KP + kc + q*8;
            u32 so = swz128((u32)(j*128 + q*16));
            cpa16(sbuf + DF_AH + so, AH + go);
            if (!pass) cpa16(sbuf + DF_AL + so, AL + go);
        }
        #pragma unroll
        for (int it = 0; it < 8; ++it) {          // X: 64 rows x 512B (4 ch x 128B)
            int e = tid + it*256;
            int k = e >> 5, q = e & 31;
            int cl = q >> 3, l8 = (q & 7)*8;
            size_t go = (size_t)cl*KLP + (size_t)(kc + k)*64 + l8;
            cpa16(sbuf + DF_X + swz512((u32)(k*512 + q*16)), X + go);
        }
    };

    float acc[4][8][4];
    #pragma unroll
    for (int i = 0; i < 4; ++i)
        #pragma unroll
        for (int j = 0; j < 8; ++j)
            #pragma unroll
            for (int q = 0; q < 4; ++q) acc[i][j][q] = 0.f;

    stage(0, sb); CP_COMMIT();
    #pragma unroll 1
    for (int c = 0; c < 4; ++c) {
        if (c < 3) { stage(c + 1, sb + ((c + 1) & 1)*DF_SZ); CP_COMMIT(); CP_WAIT1(); }
        else       { CP_WAIT0(); }
        __syncthreads();
        const u32 buf = sb + (c & 1)*DF_SZ;
        const int nk = (c == 3) ? 1 : 4;
        #pragma unroll 1
        for (int kst = 0; kst < nk; ++kst) {
            // X fragments loaded ONCE, reused across both A products
            u32 xfr[8][2];
            #pragma unroll
            for (int nj = 0; nj < 4; ++nj) {
                u32 r0, r1, r2, r3;
                ldsm4t(r0, r1, r2, r3,
                       buf + DF_X + swz512((u32)((kst*16 + (lane & 15))*512
                                           + (n0 + nj*16)*2 + (lane >> 4)*16)));
                xfr[nj*2][0] = r0; xfr[nj*2][1] = r1;
                xfr[nj*2+1][0] = r2; xfr[nj*2+1][1] = r3;
            }
            for (int p = 0; p < np; ++p) {
                const u32 aoff = p ? DF_AL : DF_AH;
                if (full) {
                    u32 afr[4][4];
                    #pragma unroll
                    for (int mi = 0; mi < 4; ++mi)
                        ldsm4(afr[mi][0], afr[mi][1], afr[mi][2], afr[mi][3],
                              buf + aoff + swz128((u32)((jm0 + mi*16 + (lane & 15))*128
                                                 + kst*32 + (lane >> 4)*16)));
                    #pragma unroll
                    for (int mi = 0; mi < 4; ++mi)
                        #pragma unroll
                        for (int ntc = 0; ntc < 8; ++ntc)
                            mma_h(acc[mi][ntc], afr[mi], xfr[ntc]);
                } else {
                    u32 afr[4];
                    ldsm4(afr[0], afr[1], afr[2], afr[3],
                          buf + aoff + swz128((u32)((jm0 + (lane & 15))*128
                                             + kst*32 + (lane >> 4)*16)));
                    #pragma unroll
                    for (int ntc = 0; ntc < 8; ++ntc)
                        mma_h(acc[0][ntc], afr, xfr[ntc]);
                }
            }
        }
        __syncthreads();
    }

    // ---- epilogue: fp32 acc -> fp16 t; warp_n owns one full channel
    __half* T = g_t16 + ((size_t)((2*s + pass)*B_DIM + b)*C_DIM + nt*4 + warp_n)*KLP;
    const int MM = full ? 4 : 1;
    #pragma unroll
    for (int mi = 0; mi < 4; ++mi) {
        if (mi >= MM) break;
        int r0 = j0 + jm0 + mi*16 + (lane >> 2);
        #pragma unroll
        for (int ntc = 0; ntc < 8; ++ntc) {
            int l = ntc*8 + (lane & 3)*2;
            *(u32*)(T + (size_t)r0*64 + l)       = cvt2h(acc[mi][ntc][0], acc[mi][ntc][1]);
            *(u32*)(T + (size_t)(r0 + 8)*64 + l) = cvt2h(acc[mi][ntc][2], acc[mi][ntc][3]);
        }
    }
}

// ================= conv: y[b][o][kl] = sum_i W[o,i] H[i][kl] + bias[o] ======
// H blocks of 64 i: [g_x16 | g_t16 m=0..3]. CTA: 256 kl x 64 o, 4 warps 64x64.
// single fp16 product. Double-buffered. 2 CTAs/SM.
#define CV_A  0         /* [64 i][256 kl] fp16, 512B rows */
#define CV_W  32768     /* [64 o][64 i] fp16, 128B rows */
#define CV_SZ 40960
#define CV_SMEM (2*CV_SZ)

__global__ __launch_bounds__(128, 2) void conv_mma(
    const float* __restrict__ bias, float* __restrict__ y)
{
    extern __shared__ char smn[];
    __shared__ float biass[64];
    const u32 sb = smem_u32(smn);
    const int tid = threadIdx.x, lane = tid & 31, wid = tid >> 5;
    const int b = blockIdx.y;
    const int kl0 = blockIdx.x * 256;
    const int klw = wid * 64;          // warp kl offset within CTA

    if (tid < 64) biass[tid] = bias[tid];

    auto stage = [&](int ch, u32 sbuf){
        const __half* Hp = (ch == 0)
            ? g_x16 + (size_t)b*C_DIM*KLP
            : g_t16 + (size_t)((ch - 1)*B_DIM + b)*C_DIM*KLP;
        #pragma unroll
        for (int it = 0; it < 16; ++it) {         // A (H^T slab): 64 rows x 512B
            int e = tid + it*128;
            int i = e >> 5, q = e & 31;
            size_t go = (size_t)i*KLP + kl0 + q*8;
            cpa16(sbuf + CV_A + swz512((u32)(i*512 + q*16)), Hp + go);
        }
        #pragma unroll
        for (int it = 0; it < 4; ++it) {          // W: 64 rows x 128B
            int e = tid + it*128;
            int o = e >> 3, q = e & 7;
            size_t go = (size_t)o*320 + ch*64 + q*8;
            cpa16(sbuf + CV_W + swz128((u32)(o*128 + q*16)), g_wh + go);
        }
    };

    float acc[4][8][4];
    #pragma unroll
    for (int i = 0; i < 4; ++i)
        #pragma unroll
        for (int j = 0; j < 8; ++j)
            #pragma unroll
            for (int q = 0; q < 4; ++q) acc[i][j][q] = 0.f;

    stage(0, sb); CP_COMMIT();
    #pragma unroll 1
    for (int c = 0; c < 5; ++c) {
        if (c < 4) { stage(c + 1, sb + ((c + 1) & 1)*CV_SZ); CP_COMMIT(); CP_WAIT1(); }
        else       { CP_WAIT0(); }
        __syncthreads();
        const u32 buf = sb + (c & 1)*CV_SZ;
        #pragma unroll 1
        for (int kst = 0; kst < 4; ++kst) {
            u32 afr[4][4];
            #pragma unroll
            for (int mi = 0; mi < 4; ++mi)
                ldsm4t(afr[mi][0], afr[mi][1], afr[mi][2], afr[mi][3],
                       buf + CV_A + swz512((u32)((kst*16 + (lane & 7)
                            + ((lane >> 4) & 1)*8)*512
                            + (klw + mi*16)*2 + ((lane >> 3) & 1)*16)));
            u32 bfr[8][2];
            #pragma unroll
            for (int nj = 0; nj < 4; ++nj) {
                u32 r0, r1, r2, r3;
                ldsm4(r0, r1, r2, r3,
                      buf + CV_W + swz128((u32)((nj*16 + (lane & 15))*128
                                         + kst*32 + (lane >> 4)*16)));
                bfr[nj*2][0] = r0; bfr[nj*2][1] = r2;
                bfr[nj*2+1][0] = r1; bfr[nj*2+1][1] = r3;
            }
            #pragma unroll
            for (int mi = 0; mi < 4; ++mi)
                #pragma unroll
                for (int ntc = 0; ntc < 8; ++ntc)
                    mma_h(acc[mi][ntc], afr[mi], bfr[ntc]);
        }
        __syncthreads();
    }

    float* yb = y + (size_t)b*C_DIM*KL;
    #pragma unroll
    for (int mi = 0; mi < 4; ++mi) {
        int kl_r = kl0 + klw + mi*16 + (lane >> 2);
        #pragma unroll
        for (int ni = 0; ni < 8; ++ni) {
            int o = ni*8 + (lane & 3)*2;
            float b0 = biass[o], b1 = biass[o + 1];
            if (kl_r < KL) {
                yb[(size_t)o*KL + kl_r]         = acc[mi][ni][0] + b0;
                yb[(size_t)(o + 1)*KL + kl_r]   = acc[mi][ni][1] + b1;
            }
            if (kl_r + 8 < KL) {
                yb[(size_t)o*KL + kl_r + 8]       = acc[mi][ni][2] + b0;
                yb[(size_t)(o + 1)*KL + kl_r + 8] = acc[mi][ni][3] + b1;
            }
        }
    }
}

// =============================================================================
extern "C" void kernel_launch(void* const* d_in, const int* in_sizes, int n_in,
                              void* d_out, int out_size) {
    const float* x    = (const float*)d_in[0];
    const float* a0   = (const float*)d_in[1];
    const float* a1   = (const float*)d_in[2];
    const float* W    = (const float*)d_in[3];
    const float* bias = (const float*)d_in[4];
    float* y = (float*)d_out;

    cudaFuncSetAttribute(diffuse_mma, cudaFuncAttributeMaxDynamicSharedMemorySize, DF_SMEM);
    cudaFuncSetAttribute(conv_mma,    cudaFuncAttributeMaxDynamicSharedMemorySize, CV_SMEM);

    prep_x<<<32768, 256>>>(x);      // B*C*KLP/2 pairs
    prep_a<<<4096, 256>>>(a0, a1);  // 2*B*KP*KP/2 pairs
    prep_w<<<40, 256>>>(W);         // 64*320/2 pairs

    diffuse_mma<<<dim3(32, 2, 16), 256, DF_SMEM>>>(0);  // A0x, A1x (2-product)
    diffuse_mma<<<dim3(32, 2, 16), 256, DF_SMEM>>>(1);  // A0^2x, A1^2x (1-product)
    conv_mma   <<<dim3(52, 16),    128, CV_SMEM>>>(bias, y);
}